// round 2
// baseline (speedup 1.0000x reference)
#include <cuda_runtime.h>
#include <math.h>

// ---------------------------------------------------------------------------
// Problem constants
// ---------------------------------------------------------------------------
constexpr int Bn  = 8;
constexpr int C   = 128;
constexpr int Hh  = 64;
constexpr int Ww  = 64;
constexpr int HW  = Hh * Ww;          // 4096
constexpr int TOK = Bn * HW;          // 32768
constexpr int VPW = 192;              // padded width of fused value+offsetmask output
constexpr float EPS = 1e-5f;

// ---------------------------------------------------------------------------
// Device scratch (static globals — no runtime allocation allowed)
// ---------------------------------------------------------------------------
__device__ float g_x1[TOK * C];        // pw0 output, NCHW memory (=token view)
__device__ float g_vpom[TOK * VPW];    // cols 0..127 value, 128..154 offset/mask
__device__ float g_dcn[TOK * C];       // DCN core output (token-major)
__device__ float g_op[TOK * C];        // after @ w_op (token-major = NCHW view)
__device__ float g_w0f[C * C];         // pw0 with BN1 folded
__device__ float g_w1f[C * C];         // pw1 with BN2 folded
__device__ float g_wcat[C * VPW];      // [w_vp | w_om[:, :27] | 0]
__device__ float g_bias0[C];
__device__ float g_bias1[C];
__device__ float g_bcat[VPW];

// ---------------------------------------------------------------------------
// Weight preparation: fold BN into pointwise convs, build concatenated weight
// ---------------------------------------------------------------------------
__global__ void prep_weights(const float* __restrict__ bn1_g, const float* __restrict__ bn1_v,
                             const float* __restrict__ bn2_g, const float* __restrict__ bn2_v,
                             const float* __restrict__ w_pw0, const float* __restrict__ w_pw1,
                             const float* __restrict__ w_vp,  const float* __restrict__ w_om,
                             const float* __restrict__ b_vp,  const float* __restrict__ b_om)
{
    const int TOTAL = 16384 + 16384 + C * VPW + VPW;   // 57536
    for (int idx = blockIdx.x * blockDim.x + threadIdx.x; idx < TOTAL;
         idx += gridDim.x * blockDim.x) {
        if (idx < 16384) {
            int c = idx & 127;
            g_w0f[idx] = w_pw0[idx] * bn1_g[c] * rsqrtf(bn1_v[c] + EPS);
        } else if (idx < 32768) {
            int j = idx - 16384;
            int c = j & 127;
            g_w1f[j] = w_pw1[j] * bn2_g[c] * rsqrtf(bn2_v[c] + EPS);
        } else if (idx < 32768 + C * VPW) {
            int j  = idx - 32768;
            int k  = j / VPW;
            int jj = j - k * VPW;
            float v;
            if (jj < 128)      v = w_vp[k * 128 + jj];
            else if (jj < 155) v = w_om[k * 32 + (jj - 128)];
            else               v = 0.f;
            g_wcat[j] = v;
        } else {
            int j = idx - (32768 + C * VPW);
            g_bcat[j] = (j < 128) ? b_vp[j] : ((j < 155) ? b_om[j - 128] : 0.f);
        }
    }
}

__global__ void prep_bias(const float* __restrict__ bn1_g, const float* __restrict__ bn1_b,
                          const float* __restrict__ bn1_m, const float* __restrict__ bn1_v,
                          const float* __restrict__ bn2_g, const float* __restrict__ bn2_b,
                          const float* __restrict__ bn2_m, const float* __restrict__ bn2_v,
                          const float* __restrict__ w_pw0, const float* __restrict__ w_pw1)
{
    int t = threadIdx.x;
    if (t < 128) {
        int o = t;
        float s = 0.f;
        for (int c = 0; c < 128; ++c) {
            float sc = bn1_g[c] * rsqrtf(bn1_v[c] + EPS);
            s += w_pw0[o * 128 + c] * (bn1_b[c] - bn1_m[c] * sc);
        }
        g_bias0[o] = s;
    } else if (t < 256) {
        int o = t - 128;
        float s = 0.f;
        for (int c = 0; c < 128; ++c) {
            float sc = bn2_g[c] * rsqrtf(bn2_v[c] + EPS);
            s += w_pw1[o * 128 + c] * (bn2_b[c] - bn2_m[c] * sc);
        }
        g_bias1[o] = s;
    }
}

// ---------------------------------------------------------------------------
// Generic K=128 fp32 GEMM.
//   C[i,j] = sum_k A[i,k] * B[k,j]  (+ optional bias_i[i] and/or bias_j[j])
// Tile: BM=128 x BN=64, full K=128 in shared memory.
// 256 threads, each computes 8(rows) x 4(cols).
// A is row-major (lda), B row-major (ldb), C row-major (ldc).
// blockIdx.z adds batch strides to B and C (A shared across z).
// ---------------------------------------------------------------------------
constexpr int BM = 128;
constexpr int BN = 64;
constexpr int SMEM_FLOATS = BM * 128 + 128 * BN;   // 24576 floats = 96 KB

__global__ void __launch_bounds__(256, 2)
gemm_k128(const float* __restrict__ A, int lda,
          const float* __restrict__ B, int ldb, long long strideB,
          float* __restrict__ Cp, int ldc, long long strideC,
          const float* __restrict__ bias_i, const float* __restrict__ bias_j)
{
    extern __shared__ float sm[];
    float* As = sm;                 // [BM][128]  row-major (i,k)
    float* Bs = sm + BM * 128;      // [128][BN]  row-major (k,j)

    const int t  = threadIdx.x;
    const int i0 = blockIdx.x * BM;
    const int j0 = blockIdx.y * BN;
    const float* Bb = B  + (long long)blockIdx.z * strideB;
    float*       Cb = Cp + (long long)blockIdx.z * strideC;

    // Load A tile (128x128) — coalesced float4, natural layout.
#pragma unroll
    for (int it = 0; it < 16; ++it) {
        int flat = it * 1024 + t * 4;
        int i = flat >> 7;
        int k = flat & 127;
        float4 v = *(const float4*)(A + (long long)(i0 + i) * lda + k);
        *(float4*)(As + i * 128 + k) = v;
    }
    // Load B tile (128x64)
#pragma unroll
    for (int it = 0; it < 8; ++it) {
        int flat = it * 1024 + t * 4;
        int k = flat >> 6;
        int j = flat & 63;
        float4 v = *(const float4*)(Bb + (long long)k * ldb + j0 + j);
        *(float4*)(Bs + k * BN + j) = v;
    }
    __syncthreads();

    const int tx = t & 15;   // 16 col-groups * 4 cols
    const int ty = t >> 4;   // 16 row-groups * 8 rows
    const float* Asr = As + (ty * 8) * 128;
    const float* Bsc = Bs + tx * 4;

    float acc[8][4];
#pragma unroll
    for (int r = 0; r < 8; ++r)
#pragma unroll
        for (int c2 = 0; c2 < 4; ++c2) acc[r][c2] = 0.f;

#pragma unroll 2
    for (int k = 0; k < 128; k += 4) {
        float4 b0 = *(const float4*)(Bsc + (k + 0) * BN);
        float4 b1 = *(const float4*)(Bsc + (k + 1) * BN);
        float4 b2 = *(const float4*)(Bsc + (k + 2) * BN);
        float4 b3 = *(const float4*)(Bsc + (k + 3) * BN);
#pragma unroll
        for (int r = 0; r < 8; ++r) {
            float4 a = *(const float4*)(Asr + r * 128 + k);
            acc[r][0] += a.x * b0.x; acc[r][1] += a.x * b0.y;
            acc[r][2] += a.x * b0.z; acc[r][3] += a.x * b0.w;
            acc[r][0] += a.y * b1.x; acc[r][1] += a.y * b1.y;
            acc[r][2] += a.y * b1.z; acc[r][3] += a.y * b1.w;
            acc[r][0] += a.z * b2.x; acc[r][1] += a.z * b2.y;
            acc[r][2] += a.z * b2.z; acc[r][3] += a.z * b2.w;
            acc[r][0] += a.w * b3.x; acc[r][1] += a.w * b3.y;
            acc[r][2] += a.w * b3.z; acc[r][3] += a.w * b3.w;
        }
    }

    const int j = j0 + tx * 4;
    float bj0 = 0.f, bj1 = 0.f, bj2 = 0.f, bj3 = 0.f;
    if (bias_j) { bj0 = bias_j[j]; bj1 = bias_j[j + 1]; bj2 = bias_j[j + 2]; bj3 = bias_j[j + 3]; }
#pragma unroll
    for (int r = 0; r < 8; ++r) {
        int i = i0 + ty * 8 + r;
        float bi = bias_i ? bias_i[i] : 0.f;
        float4 o;
        o.x = acc[r][0] + bi + bj0;
        o.y = acc[r][1] + bi + bj1;
        o.z = acc[r][2] + bi + bj2;
        o.w = acc[r][3] + bi + bj3;
        *(float4*)(Cb + (long long)i * ldc + j) = o;
    }
}

// ---------------------------------------------------------------------------
// DCNv4 core: one warp per output position, lane handles 4 channels.
// value + (dx,dy,mask) both live in g_vpom (stride VPW).
// ---------------------------------------------------------------------------
__global__ void dcn_kernel(const float* __restrict__ vpom, float* __restrict__ out)
{
    const int warp = threadIdx.x >> 5;
    const int lane = threadIdx.x & 31;
    const int pos  = blockIdx.x * 8 + warp;          // 0..32767
    const int b = pos >> 12;
    const int s = pos & 4095;
    const int h = s >> 6;
    const int w = s & 63;

    const float* omp = vpom + (size_t)pos * VPW + 128;
    float omv = (lane < 27) ? omp[lane] : 0.f;

    const float* vb = vpom + ((size_t)b << 12) * VPW;
    const int coff = lane << 2;

    float4 acc = make_float4(0.f, 0.f, 0.f, 0.f);

#pragma unroll
    for (int k = 0; k < 9; ++k) {
        float dx = __shfl_sync(0xffffffffu, omv, 3 * k);
        float dy = __shfl_sync(0xffffffffu, omv, 3 * k + 1);
        float m  = __shfl_sync(0xffffffffu, omv, 3 * k + 2);
        float px = (float)(w + (k % 3) - 1) + dx;
        float py = (float)(h + (k / 3) - 1) + dy;
        float xf = floorf(px), yf = floorf(py);
        float fx = px - xf,    fy = py - yf;
        int x0 = (int)xf, y0 = (int)yf;
#pragma unroll
        for (int cy = 0; cy < 2; ++cy) {
#pragma unroll
            for (int cx = 0; cx < 2; ++cx) {
                int xi = x0 + cx, yi = y0 + cy;
                float wt = (cx ? fx : 1.f - fx) * (cy ? fy : 1.f - fy) * m;
                if (xi < 0 || xi > 63 || yi < 0 || yi > 63) wt = 0.f;
                int xc = min(max(xi, 0), 63);
                int yc = min(max(yi, 0), 63);
                const float4 v = *(const float4*)(vb + (size_t)(yc * 64 + xc) * VPW + coff);
                acc.x += wt * v.x; acc.y += wt * v.y;
                acc.z += wt * v.z; acc.w += wt * v.w;
            }
        }
    }
    *(float4*)(out + (size_t)pos * 128 + coff) = acc;
}

// ---------------------------------------------------------------------------
// Launcher
// ---------------------------------------------------------------------------
extern "C" void kernel_launch(void* const* d_in, const int* in_sizes, int n_in,
                              void* d_out, int out_size)
{
    (void)in_sizes; (void)n_in; (void)out_size;
    const float* x     = (const float*)d_in[0];
    const float* bn1_g = (const float*)d_in[1];
    const float* bn1_b = (const float*)d_in[2];
    const float* bn1_m = (const float*)d_in[3];
    const float* bn1_v = (const float*)d_in[4];
    const float* w_pw0 = (const float*)d_in[5];
    const float* w_vp  = (const float*)d_in[6];
    const float* b_vp  = (const float*)d_in[7];
    const float* w_om  = (const float*)d_in[8];
    const float* b_om  = (const float*)d_in[9];
    const float* w_op  = (const float*)d_in[10];
    const float* bn2_g = (const float*)d_in[11];
    const float* bn2_b = (const float*)d_in[12];
    const float* bn2_m = (const float*)d_in[13];
    const float* bn2_v = (const float*)d_in[14];
    const float* w_pw1 = (const float*)d_in[15];
    float* out = (float*)d_out;

    float *x1, *vpom, *dcn, *op, *w0f, *w1f, *wcat, *bias0, *bias1, *bcat;
    cudaGetSymbolAddress((void**)&x1,    g_x1);
    cudaGetSymbolAddress((void**)&vpom,  g_vpom);
    cudaGetSymbolAddress((void**)&dcn,   g_dcn);
    cudaGetSymbolAddress((void**)&op,    g_op);
    cudaGetSymbolAddress((void**)&w0f,   g_w0f);
    cudaGetSymbolAddress((void**)&w1f,   g_w1f);
    cudaGetSymbolAddress((void**)&wcat,  g_wcat);
    cudaGetSymbolAddress((void**)&bias0, g_bias0);
    cudaGetSymbolAddress((void**)&bias1, g_bias1);
    cudaGetSymbolAddress((void**)&bcat,  g_bcat);

    const int SMEM_BYTES = SMEM_FLOATS * sizeof(float);   // 98304
    cudaFuncSetAttribute(gemm_k128, cudaFuncAttributeMaxDynamicSharedMemorySize, SMEM_BYTES);

    // 0) weight prep
    prep_weights<<<112, 512>>>(bn1_g, bn1_v, bn2_g, bn2_v, w_pw0, w_pw1, w_vp, w_om, b_vp, b_om);
    prep_bias<<<1, 256>>>(bn1_g, bn1_b, bn1_m, bn1_v, bn2_g, bn2_b, bn2_m, bn2_v, w_pw0, w_pw1);

    // 1) x1 = (BN1-folded pw0) @ x, NCHW layout. per-batch: (128x128)@(128x4096)
    gemm_k128<<<dim3(1, 64, 8), 256, SMEM_BYTES>>>(
        w0f, 128, x, 4096, (long long)C * HW, x1, 4096, (long long)C * HW, bias0, nullptr);

    // 2) vpom = x1_view(32768,128) @ wcat(128,192) + bcat
    gemm_k128<<<dim3(TOK / BM, VPW / BN, 1), 256, SMEM_BYTES>>>(
        x1, 128, wcat, VPW, 0, vpom, VPW, 0, nullptr, bcat);

    // 3) DCNv4 core
    dcn_kernel<<<TOK / 8, 256>>>(vpom, dcn);

    // 4) op = dcn(32768,128) @ w_op(128,128)
    gemm_k128<<<dim3(TOK / BM, C / BN, 1), 256, SMEM_BYTES>>>(
        dcn, 128, w_op, 128, 0, op, 128, 0, nullptr, nullptr);

    // 5) out = (BN2-folded pw1) @ op_view, NCHW. per-batch: (128x128)@(128x4096)
    gemm_k128<<<dim3(1, 64, 8), 256, SMEM_BYTES>>>(
        w1f, 128, op, 4096, (long long)C * HW, out, 4096, (long long)C * HW, bias1, nullptr);
}